// round 16
// baseline (speedup 1.0000x reference)
#include <cuda_runtime.h>
#include <cuda_bf16.h>
#include <cstdint>
#include <math.h>

// Problem constants
constexpr int BS = 16, C = 64, H = 128, W = 128;
constexpr int HW = H * W;           // 16384
constexpr int NC = 80;
constexpr int TOPK = 128;
constexpr int CAP = 4096;           // candidate buffer per batch (global)
constexpr int SCAP = 2048;          // candidate keys rankable in smem
constexpr float CAND_T = 0.999f;    // prefilter threshold

// Scratch (device globals; no allocation allowed)
__device__ int                g_peak[BS * NC];
__device__ float              g_cmask[BS * NC];
__device__ float              g_hmfree[BS * HW];
__device__ float              g_maxval[BS * HW];
__device__ int                g_argcls[BS * HW];
__device__ int                g_ccount[BS];
__device__ int                g_batch_done[BS];
__device__ unsigned long long g_cand[BS * CAP];
__device__ int                g_cand_cls[BS * CAP];
__device__ int                g_topk_idx[BS * TOPK];
__device__ float              g_topk_val[BS * TOPK];
__device__ int                g_topk_cls[BS * TOPK];
__device__ float              g_loss_sum;
__device__ float              g_loss_cnt;
__device__ int                g_loss_done;

// ---------------------------------------------------------------------------
__global__ void init_kernel() {
    int t = blockIdx.x * blockDim.x + threadIdx.x;
    if (t < BS * NC) { g_peak[t] = -1; g_cmask[t] = 0.f; }
    if (t < BS) { g_ccount[t] = 0; g_batch_done[t] = 0; }
    if (t == 0) { g_loss_sum = 0.f; g_loss_cnt = 0.f; g_loss_done = 0; }
}

// ---------------------------------------------------------------------------
// Scan hm: peaks, class_mask, hm_free. Also zeroes the FIRST half of the
// output buffer (other half is zeroed by score_kernel -> balanced traffic).
__global__ void hm_kernel(const float* __restrict__ hm,
                          float* __restrict__ out, int out_size) {
    int t  = blockIdx.x * blockDim.x + threadIdx.x;
    int b  = t >> 12;
    int p4 = (t & 4095) << 2;
    const float* base = hm + (size_t)b * NC * HW + p4;
    float f0 = 1.f, f1 = 1.f, f2 = 1.f, f3 = 1.f;
#pragma unroll
    for (int cc = 0; cc < NC; cc += 8) {
        float4 r[8];
#pragma unroll
        for (int j = 0; j < 8; j++)
            r[j] = *reinterpret_cast<const float4*>(base + (cc + j) * HW);
#pragma unroll
        for (int j = 0; j < 8; j++) {
            int c = cc + j;
            if (r[j].x == 1.f) { f0 = 0.f; g_peak[b*NC+c] = p4;     g_cmask[b*NC+c] = 1.f; }
            if (r[j].y == 1.f) { f1 = 0.f; g_peak[b*NC+c] = p4 + 1; g_cmask[b*NC+c] = 1.f; }
            if (r[j].z == 1.f) { f2 = 0.f; g_peak[b*NC+c] = p4 + 2; g_cmask[b*NC+c] = 1.f; }
            if (r[j].w == 1.f) { f3 = 0.f; g_peak[b*NC+c] = p4 + 3; g_cmask[b*NC+c] = 1.f; }
        }
    }
    *reinterpret_cast<float4*>(&g_hmfree[b * HW + p4]) = make_float4(f0, f1, f2, f3);

    // Zero first half of output (float4 grid-stride).
    int   n4  = out_size >> 2;
    int   n4h = n4 >> 1;
    float4* o4 = reinterpret_cast<float4*>(out);
    const float4 z4 = make_float4(0.f, 0.f, 0.f, 0.f);
    for (int i = t; i < n4h; i += 65536) o4[i] = z4;
}

// ---------------------------------------------------------------------------
// Masked per-pixel max/argmax over classes (first-max semantics), PLUS:
//  - candidate prefilter (maxval >= CAND_T -> packed candidate list)
//  - zeroing of the SECOND half of the output buffer
//  - FUSED RANK TAIL: the last-finishing block of each batch (per-batch
//    ticket) ranks that batch's candidates in smem and writes g_topk_*.
__device__ __forceinline__ void add_candidate(int b, float m, int idx, int cls) {
    if (m >= CAND_T) {
        int pos = atomicAdd(&g_ccount[b], 1);
        if (pos < CAP) {
            unsigned vb = __float_as_uint(m);
            g_cand[b * CAP + pos] =
                ((unsigned long long)vb << 14) | (unsigned)(16383 - idx);
            g_cand_cls[b * CAP + pos] = cls;
        }
    }
}

__global__ void score_kernel(const float* __restrict__ score,
                             float* __restrict__ out, int out_size) {
    __shared__ float scm[NC];
    __shared__ unsigned long long sbuf[SCAP + 8];
    __shared__ int s_last;
    __shared__ int s_warp[8];
    __shared__ int s_tot;
    const int tid = threadIdx.x, lane = tid & 31, wid = tid >> 5;
    int b  = blockIdx.x >> 4;
    int p4 = ((((blockIdx.x & 15) << 8) + tid)) << 2;
    if (tid < NC) scm[tid] = g_cmask[b * NC + tid];
    __syncthreads();
    float4 hf = *reinterpret_cast<const float4*>(&g_hmfree[b * HW + p4]);
    const float* base = score + (size_t)b * NC * HW + p4;
    float m0 = 0.f, m1 = 0.f, m2 = 0.f, m3 = 0.f;
    int   c0 = 0,   c1 = 0,   c2 = 0,   c3 = 0;
#pragma unroll
    for (int cc = 0; cc < NC; cc += 8) {
        float4 r[8];
#pragma unroll
        for (int j = 0; j < 8; j++)
            r[j] = *reinterpret_cast<const float4*>(base + (cc + j) * HW);
#pragma unroll
        for (int j = 0; j < 8; j++) {
            int c = cc + j;
            float cm = scm[c];
            float s0 = r[j].x * cm * hf.x; if (s0 > m0) { m0 = s0; c0 = c; }
            float s1 = r[j].y * cm * hf.y; if (s1 > m1) { m1 = s1; c1 = c; }
            float s2 = r[j].z * cm * hf.z; if (s2 > m2) { m2 = s2; c2 = c; }
            float s3 = r[j].w * cm * hf.w; if (s3 > m3) { m3 = s3; c3 = c; }
        }
    }
    *reinterpret_cast<float4*>(&g_maxval[b * HW + p4]) = make_float4(m0, m1, m2, m3);
    *reinterpret_cast<int4*>(&g_argcls[b * HW + p4])   = make_int4(c0, c1, c2, c3);

    add_candidate(b, m0, p4,     c0);
    add_candidate(b, m1, p4 + 1, c1);
    add_candidate(b, m2, p4 + 2, c2);
    add_candidate(b, m3, p4 + 3, c3);

    // Zero second half of output (float4 grid-stride) + tail.
    {
        int   gtid = blockIdx.x * 256 + tid;
        int   n4   = out_size >> 2;
        int   n4h  = n4 >> 1;
        float4* o4 = reinterpret_cast<float4*>(out);
        const float4 z4 = make_float4(0.f, 0.f, 0.f, 0.f);
        for (int i = n4h + gtid; i < n4; i += 65536) o4[i] = z4;
        if (gtid == 0)
            for (int i = n4 << 2; i < out_size; i++) out[i] = 0.f;
    }

    // ---- per-batch ticket: last of the 16 blocks of batch b ranks it ----
    __threadfence();
    if (tid == 0)
        s_last = (atomicAdd(&g_batch_done[b], 1) == 15);
    __syncthreads();
    if (!s_last) return;

    const int M = g_ccount[b];
    if (M >= TOPK && M <= SCAP) {
        // Pairwise rank of M packed (value, 16383-idx) keys; 8x unrolled over
        // zero-padded array (0 never outranks a real key). rank r<128 -> slot r.
        const int Mpad = (M + 7) & ~7;
        for (int i = tid; i < Mpad; i += 256)
            sbuf[i] = (i < M) ? g_cand[b * CAP + i] : 0ULL;
        __syncthreads();
        for (int i = tid; i < M; i += 256) {
            unsigned long long me = sbuf[i];
            int r = 0;
            for (int j = 0; j < Mpad; j += 8) {
                unsigned long long k0 = sbuf[j    ], k1 = sbuf[j + 1];
                unsigned long long k2 = sbuf[j + 2], k3 = sbuf[j + 3];
                unsigned long long k4 = sbuf[j + 4], k5 = sbuf[j + 5];
                unsigned long long k6 = sbuf[j + 6], k7 = sbuf[j + 7];
                r += (k0 > me) + (k1 > me) + (k2 > me) + (k3 > me)
                   + (k4 > me) + (k5 > me) + (k6 > me) + (k7 > me);
            }
            if (r < TOPK) {
                unsigned vb = (unsigned)(me >> 14);
                int idx = 16383 - (int)(me & 16383u);
                g_topk_val[b * TOPK + r] = __uint_as_float(vb);
                g_topk_idx[b * TOPK + r] = idx;
                g_topk_cls[b * TOPK + r] = g_cand_cls[b * CAP + i];
            }
        }
        return;
    }

    // ---- Fallback (cold): exact binary search over all 16384 values ----
    const unsigned* mv = reinterpret_cast<const unsigned*>(g_maxval) + b * HW;

    auto blockCount = [&](unsigned thr, bool strict) -> int {
        __syncthreads();
        int c = 0;
        for (int i = 0; i < 64; i++) {
            unsigned x = mv[i * 256 + tid];
            c += strict ? (x > thr) : (x >= thr);
        }
        for (int o = 16; o; o >>= 1) c += __shfl_xor_sync(0xffffffffu, c, o);
        if (lane == 0) s_warp[wid] = c;
        __syncthreads();
        if (tid == 0) {
            int t2 = 0;
            for (int w = 0; w < 8; w++) t2 += s_warp[w];
            s_tot = t2;
        }
        __syncthreads();
        return s_tot;
    };

    auto blockScanExcl = [&](int x) -> int {
        __syncthreads();
        int incl = x;
        for (int o = 1; o < 32; o <<= 1) {
            int t2 = __shfl_up_sync(0xffffffffu, incl, o);
            if (lane >= o) incl += t2;
        }
        if (lane == 31) s_warp[wid] = incl;
        __syncthreads();
        if (tid < 8) {
            int t2 = s_warp[tid];
            int inc2 = t2;
            for (int o = 1; o < 8; o <<= 1) {
                int u = __shfl_up_sync(0x000000ffu, inc2, o);
                if (tid >= o) inc2 += u;
            }
            s_warp[tid] = inc2 - t2;
        }
        __syncthreads();
        return s_warp[wid] + incl - x;
    };

    unsigned lo = 0, hi = 0x3F800000u;
    while (lo < hi) {
        unsigned mid = lo + ((hi - lo + 1) >> 1);
        int c = blockCount(mid, false);
        if (c >= TOPK) lo = mid; else hi = mid - 1;
    }
    unsigned V = lo;
    int G  = blockCount(V, true);
    int En = TOPK - G;

    int cgt = 0;
    for (int i = 0; i < 64; i++) cgt += (mv[i * 256 + tid] > V);
    int slot = blockScanExcl(cgt);
    for (int i = 0; i < 64; i++) {
        unsigned x = mv[i * 256 + tid];
        if (x > V) {
            int idx = i * 256 + tid;
            g_topk_val[b * TOPK + slot] = __uint_as_float(x);
            g_topk_idx[b * TOPK + slot] = idx;
            g_topk_cls[b * TOPK + slot] = g_argcls[b * HW + idx];
            slot++;
        }
    }
    int ceq = 0;
    for (int i = 0; i < 64; i++) ceq += (mv[i * 256 + tid] == V);
    int r = blockScanExcl(ceq);
    for (int i = 0; i < 64; i++) {
        unsigned x = mv[i * 256 + tid];
        if (x == V) {
            if (r < En) {
                int idx = i * 256 + tid;
                int s2 = G + r;
                g_topk_val[b * TOPK + s2] = __uint_as_float(x);
                g_topk_idx[b * TOPK + s2] = idx;
                g_topk_cls[b * TOPK + s2] = g_argcls[b * HW + idx];
            }
            r++;
        }
    }
}

// ---------------------------------------------------------------------------
// Fused gather + contrastive loss + final reduction.
// Block = (batch, 8-class group). Each block gathers + L2-normalizes its
// batch's key rows from feat directly into ITS OWN smem (topk rows + k0/q
// rows; ~10x redundant global reads, L2-resident), computes the loss for its
// 8 query classes, and atomically accumulates (sum, count). ng==0 blocks
// also scatter the 0.9 pseudo-hm entries. Last block writes out[0].
__global__ void loss_kernel(const float* __restrict__ feat, float* __restrict__ out) {
    __shared__ float buf[TOPK * C];     // 32 KB (topk rows, then reused for k0)
    __shared__ float qs[8 * C];         // 2 KB query rows
    __shared__ float cmsh[NC];
    __shared__ float r_s[8], r_d[8], r_n[8];
    __shared__ float acc_s[8], acc_d[8], acc_n[8];
    __shared__ float s_ls, s_lc;
    const int b   = blockIdx.x / 10;
    const int ng  = blockIdx.x % 10;
    const int tid = threadIdx.x, lane = tid & 31, wid = tid >> 5;
    const float* fb = feat + (size_t)b * C * HW;

    if (tid == 0) { s_ls = 0.f; s_lc = 0.f; }
    if (tid < NC) cmsh[tid] = g_cmask[b * NC + tid];

    // P1: gather the 8 query rows (peaks of classes ng*8..ng*8+7).
    {
        int n = ng * 8 + wid;
        int p = g_peak[b * NC + n];
        float a = 0.f, b2 = 0.f;
        if (p >= 0) {
            a  = fb[(size_t)lane * HW + p];
            b2 = fb[(size_t)(lane + 32) * HW + p];
            float ss = a * a + b2 * b2;
#pragma unroll
            for (int o = 16; o; o >>= 1) ss += __shfl_xor_sync(0xffffffffu, ss, o);
            float inv = 1.f / fmaxf(sqrtf(ss), 1e-12f);
            a *= inv; b2 *= inv;
        }
        qs[wid * C + lane] = a;
        qs[wid * C + lane + 32] = b2;
    }

    // P2: gather the 128 topk key rows; ng==0 blocks scatter pseudo-hm 0.9.
#pragma unroll 1
    for (int k = 0; k < 16; k++) {
        int s = wid + 8 * k;
        int p = g_topk_idx[b * TOPK + s];
        float a  = fb[(size_t)lane * HW + p];
        float b2 = fb[(size_t)(lane + 32) * HW + p];
        float ss = a * a + b2 * b2;
#pragma unroll
        for (int o = 16; o; o >>= 1) ss += __shfl_xor_sync(0xffffffffu, ss, o);
        float inv = 1.f / fmaxf(sqrtf(ss), 1e-12f);
        buf[s * C + lane] = a * inv;
        buf[s * C + lane + 32] = b2 * inv;
        if (ng == 0 && lane == 0 && g_topk_val[b * TOPK + s] > 0.f)
            out[1 + (size_t)(b * NC + g_topk_cls[b * TOPK + s]) * HW + p] = 0.9f;
    }

    float kvalA = 0.f; int kclsA = -1;
    if (tid < TOPK) {
        kvalA = g_topk_val[b * TOPK + tid];
        kclsA = g_topk_cls[b * TOPK + tid];
    }
    __syncthreads();

    // ---- chunk A: 128 topk keys ----
    float mallA = (kvalA > 0.f) ? 1.f : 0.f;
    for (int nl = 0; nl < 8; nl++) {
        int n = ng * 8 + nl;
        float ssum = 0.f, dsum = 0.f, num = 0.f;
        if (tid < TOPK) {
            float d = 0.f;
            const float* kr = buf + tid * C;
            const float* qr = qs + nl * C;
#pragma unroll
            for (int c = 0; c < C; c++) {
                int cc = (c + tid) & (C - 1);
                d += kr[cc] * qr[cc];
            }
            float dt = d / 0.07f;
            float mm = (kclsA == n && kvalA > 0.f) ? 1.f : 0.f;
            ssum = expf(dt) * mallA;
            dsum = dt * mm;
            num  = mm;
        }
        for (int o = 16; o; o >>= 1) {
            ssum += __shfl_xor_sync(0xffffffffu, ssum, o);
            dsum += __shfl_xor_sync(0xffffffffu, dsum, o);
            num  += __shfl_xor_sync(0xffffffffu, num,  o);
        }
        if (lane == 0) { r_s[wid] = ssum; r_d[wid] = dsum; r_n[wid] = num; }
        __syncthreads();
        if (tid == 0) {
            float S = 0.f, D = 0.f, N = 0.f;
            for (int w = 0; w < 8; w++) { S += r_s[w]; D += r_d[w]; N += r_n[w]; }
            acc_s[nl] = S; acc_d[nl] = D; acc_n[nl] = N;
        }
        __syncthreads();
    }

    // P3: gather the 80 k0 rows (== q rows) into buf (reuse).
#pragma unroll 1
    for (int k = 0; k < 10; k++) {
        int n2 = wid + 8 * k;
        if (n2 < NC) {
            int p = g_peak[b * NC + n2];
            float a = 0.f, b2 = 0.f;
            if (p >= 0) {
                a  = fb[(size_t)lane * HW + p];
                b2 = fb[(size_t)(lane + 32) * HW + p];
                float ss = a * a + b2 * b2;
#pragma unroll
                for (int o = 16; o; o >>= 1) ss += __shfl_xor_sync(0xffffffffu, ss, o);
                float inv = 1.f / fmaxf(sqrtf(ss), 1e-12f);
                a *= inv; b2 *= inv;
            }
            buf[n2 * C + lane] = a;
            buf[n2 * C + lane + 32] = b2;
        }
    }
    __syncthreads();

    // ---- chunk B: 80 k0 keys ----
    float mallB = (tid < NC) ? cmsh[tid] : 0.f;
    for (int nl = 0; nl < 8; nl++) {
        int n = ng * 8 + nl;
        float cm = cmsh[n];
        float ssum = 0.f, dsum = 0.f, num = 0.f;
        if (tid < NC) {
            float d = 0.f;
            const float* kr = buf + tid * C;
            const float* qr = qs + nl * C;
#pragma unroll
            for (int c = 0; c < C; c++) {
                int cc = (c + tid) & (C - 1);
                d += kr[cc] * qr[cc];
            }
            float dt = d / 0.07f;
            float mm = (tid == n) ? cm : 0.f;   // k0_mask diagonal
            ssum = expf(dt) * mallB;
            dsum = dt * mm;
            num  = mm;
        }
        for (int o = 16; o; o >>= 1) {
            ssum += __shfl_xor_sync(0xffffffffu, ssum, o);
            dsum += __shfl_xor_sync(0xffffffffu, dsum, o);
            num  += __shfl_xor_sync(0xffffffffu, num,  o);
        }
        if (lane == 0) { r_s[wid] = ssum; r_d[wid] = dsum; r_n[wid] = num; }
        __syncthreads();
        if (tid == 0) {
            float S = acc_s[nl], D = acc_d[nl], N = acc_n[nl];
            for (int w = 0; w < 8; w++) { S += r_s[w]; D += r_d[w]; N += r_n[w]; }
            if (cm != 0.f) {
                s_ls += (D - N * logf(S)) / N;  // N >= 1 (diagonal)
                s_lc += cm;
            }
        }
        __syncthreads();
    }

    if (tid == 0) {
        atomicAdd(&g_loss_sum, s_ls);
        atomicAdd(&g_loss_cnt, s_lc);
        __threadfence();
        int done = atomicAdd(&g_loss_done, 1);
        if (done == BS * 10 - 1) {
            out[0] = -(g_loss_sum / g_loss_cnt);
        }
    }
}

// ---------------------------------------------------------------------------
extern "C" void kernel_launch(void* const* d_in, const int* in_sizes, int n_in,
                              void* d_out, int out_size) {
    const float* feat  = (const float*)d_in[0];
    const float* score = (const float*)d_in[1];
    const float* hm    = (const float*)d_in[2];
    float* out = (float*)d_out;

    // Output layout: [ -loss (1 float), pseudo_hm (16*80*128*128 floats) ]
    init_kernel<<<(BS * NC + 255) / 256, 256>>>();
    hm_kernel<<<BS * (HW / 4) / 256, 256>>>(hm, out, out_size);
    score_kernel<<<BS * 16, 256>>>(score, out, out_size);
    loss_kernel<<<BS * 10, 256>>>(feat, out);
}